// round 10
// baseline (speedup 1.0000x reference)
#include <cuda_runtime.h>

// x: (4096, 8192) fp32, row-major. p = x[:, :4096], q = x[:, 4096:].
// out[:, :4096] = p
// out[:, 4096:] = weight[row] * selu(p) + q
//
// R3 structure exactly (best kernel: 35.7us, DRAM 75.4%), with the single
// variable block=512 (halves resident CTA count per SM; identical per-thread
// access pattern, default cache policy everywhere).

#define SIZE   4096
#define HALF4  (SIZE / 4)          // 1024 float4 per half-row
#define ROWLEN (2 * SIZE)          // 8192 floats per x row

__device__ __forceinline__ float selu_f(float v) {
    const float SCALE = 1.0507009873554804934193349852946f;
    const float ALPHA = 1.6732632423543772848170429916717f;
    float neg = SCALE * ALPHA * (__expf(fminf(v, 0.0f)) - 1.0f);
    float pos = SCALE * v;
    return v > 0.0f ? pos : neg;
}

__global__ __launch_bounds__(512) void selu_fuse_kernel(
    const float4* __restrict__ x,
    const float*  __restrict__ weight,
    float4*       __restrict__ out)
{
    long long i = (long long)blockIdx.x * blockDim.x + threadIdx.x;

    int row  = (int)(i >> 10);          // i / 1024
    int col4 = (int)(i & 1023);         // i % 1024

    const float4* prow = x + (long long)row * (ROWLEN / 4);
    float4 p = prow[col4];
    float4 q = prow[col4 + HALF4];

    float w = __ldg(weight + row);

    float4 r;
    r.x = fmaf(w, selu_f(p.x), q.x);
    r.y = fmaf(w, selu_f(p.y), q.y);
    r.z = fmaf(w, selu_f(p.z), q.z);
    r.w = fmaf(w, selu_f(p.w), q.w);

    float4* orow = out + (long long)row * (ROWLEN / 4);
    orow[col4]         = p;   // pass-through first half
    orow[col4 + HALF4] = r;   // fused second half
}

extern "C" void kernel_launch(void* const* d_in, const int* in_sizes, int n_in,
                              void* d_out, int out_size)
{
    const float4* x = (const float4*)d_in[0];
    const float*  w = (const float*)d_in[1];
    float4* out = (float4*)d_out;

    const int total4 = SIZE * HALF4;        // 4,194,304 threads
    const int block = 512;
    const int grid  = total4 / block;       // 8192

    selu_fuse_kernel<<<grid, block>>>(x, w, out);
}

// round 12
// speedup vs baseline: 1.0162x; 1.0162x over previous
#include <cuda_runtime.h>

// x: (4096, 8192) fp32, row-major. p = x[:, :4096], q = x[:, 4096:].
// out[:, :4096] = p
// out[:, 4096:] = weight[row] * selu(p) + q
//
// Best-known structure (one float4-pair per thread, default cache policy).
// Single variable vs R9: block=1024 (2 resident CTAs/SM).

#define SIZE   4096
#define HALF4  (SIZE / 4)          // 1024 float4 per half-row
#define ROWLEN (2 * SIZE)          // 8192 floats per x row

__device__ __forceinline__ float selu_f(float v) {
    const float SCALE = 1.0507009873554804934193349852946f;
    const float ALPHA = 1.6732632423543772848170429916717f;
    float neg = SCALE * ALPHA * (__expf(fminf(v, 0.0f)) - 1.0f);
    float pos = SCALE * v;
    return v > 0.0f ? pos : neg;
}

__global__ __launch_bounds__(1024) void selu_fuse_kernel(
    const float4* __restrict__ x,
    const float*  __restrict__ weight,
    float4*       __restrict__ out)
{
    long long i = (long long)blockIdx.x * blockDim.x + threadIdx.x;

    int row  = (int)(i >> 10);          // i / 1024
    int col4 = (int)(i & 1023);         // i % 1024

    const float4* prow = x + (long long)row * (ROWLEN / 4);
    float4 p = prow[col4];
    float4 q = prow[col4 + HALF4];

    float w = __ldg(weight + row);

    float4 r;
    r.x = fmaf(w, selu_f(p.x), q.x);
    r.y = fmaf(w, selu_f(p.y), q.y);
    r.z = fmaf(w, selu_f(p.z), q.z);
    r.w = fmaf(w, selu_f(p.w), q.w);

    float4* orow = out + (long long)row * (ROWLEN / 4);
    orow[col4]         = p;   // pass-through first half
    orow[col4 + HALF4] = r;   // fused second half
}

extern "C" void kernel_launch(void* const* d_in, const int* in_sizes, int n_in,
                              void* d_out, int out_size)
{
    const float4* x = (const float4*)d_in[0];
    const float*  w = (const float*)d_in[1];
    float4* out = (float4*)d_out;

    const int total4 = SIZE * HALF4;        // 4,194,304 threads
    const int block = 1024;
    const int grid  = total4 / block;       // 4096

    selu_fuse_kernel<<<grid, block>>>(x, w, out);
}